// round 13
// baseline (speedup 1.0000x reference)
#include <cuda_runtime.h>
#include <cuda_fp16.h>
#include <cstdint>

#define NB    4
#define TSEQ  2048
#define CDIM  1024
#define HEADS 16
#define HD    64
#define BT    (NB*TSEQ)          // 8192
#define NQKV  3072

// Q pre-scale: 1/sqrt(64) * log2(e)  (softmax in base-2 domain)
#define QSCALE (0.125f * 1.44269504088896f)

// ---------------------------------------------------------------------------
// __device__ global scratch
// ---------------------------------------------------------------------------
__device__ __half g_xh[(size_t)BT*CDIM];
__device__ __half g_wh[(size_t)NQKV*CDIM];
// Q fp16 (scaled), K fp16, V fp16 — all [B,H,T,D]
__device__ __half g_qh[(size_t)NB*HEADS*TSEQ*HD];
__device__ __half g_kh[(size_t)NB*HEADS*TSEQ*HD];
__device__ __half g_vh[(size_t)NB*HEADS*TSEQ*HD];

// ---------------------------------------------------------------------------
// Helpers
// ---------------------------------------------------------------------------
__device__ __forceinline__ uint32_t smem_to_u32(const void* p) {
    uint32_t a;
    asm("{ .reg .u64 t; cvta.to.shared.u64 t, %1; cvt.u32.u64 %0, t; }" : "=r"(a) : "l"(p));
    return a;
}
#define CP_ASYNC(dst, src) \
    asm volatile("cp.async.cg.shared.global [%0], [%1], 16;\n" :: "r"(dst), "l"(src))
#define CP_COMMIT() asm volatile("cp.async.commit_group;\n" ::: "memory")
#define CP_WAIT1()  asm volatile("cp.async.wait_group 1;\n" ::: "memory")
#define CP_WAIT0()  asm volatile("cp.async.wait_group 0;\n" ::: "memory")

__device__ __forceinline__ void ldsm4(uint32_t r[4], uint32_t a) {
    asm volatile("ldmatrix.sync.aligned.m8n8.x4.shared.b16 {%0,%1,%2,%3}, [%4];"
                 : "=r"(r[0]), "=r"(r[1]), "=r"(r[2]), "=r"(r[3]) : "r"(a));
}
__device__ __forceinline__ void ldsm4t(uint32_t r[4], uint32_t a) {
    asm volatile("ldmatrix.sync.aligned.m8n8.x4.trans.shared.b16 {%0,%1,%2,%3}, [%4];"
                 : "=r"(r[0]), "=r"(r[1]), "=r"(r[2]), "=r"(r[3]) : "r"(a));
}
__device__ __forceinline__ void mma_f16(float c[4], const uint32_t a[4],
                                        uint32_t b0, uint32_t b1) {
    asm volatile("mma.sync.aligned.m16n8k16.row.col.f32.f16.f16.f32 "
                 "{%0,%1,%2,%3}, {%4,%5,%6,%7}, {%8,%9}, {%0,%1,%2,%3};"
                 : "+f"(c[0]), "+f"(c[1]), "+f"(c[2]), "+f"(c[3])
                 : "r"(a[0]), "r"(a[1]), "r"(a[2]), "r"(a[3]), "r"(b0), "r"(b1));
}
__device__ __forceinline__ uint32_t pack2h(__half a, __half b) {
    __half2 t(a, b);
    return *reinterpret_cast<uint32_t*>(&t);
}

// ---------------------------------------------------------------------------
// Kernel 0: fused fp32 -> fp16 convert (coalesced, 1 float4/thread — R10 form)
// ---------------------------------------------------------------------------
__global__ __launch_bounds__(256) void conv_all(const float* __restrict__ x,
                                                const float* __restrict__ w,
                                                int nx4, int nw4)
{
    int i = blockIdx.x * 256 + threadIdx.x;
    const float* src;
    __half2* dp;
    int j;
    if (i < nx4) {
        src = x; dp = (__half2*)g_xh; j = i;
    } else {
        j = i - nx4;
        if (j >= nw4) return;
        src = w; dp = (__half2*)g_wh;
    }
    float4 v = ((const float4*)src)[j];
    dp[2*j]   = __half2(__float2half(v.x), __float2half(v.y));
    dp[2*j+1] = __half2(__float2half(v.z), __float2half(v.w));
}

// ---------------------------------------------------------------------------
// Kernel 1: QKV GEMM = xh * wh, single fp16 MMA (fp32 accum) per product.
// CTA 128x128, 4 warps (64x64), KC=64 double-buffered, 3 CTAs/SM. (R11 form)
// ---------------------------------------------------------------------------
#define KCG      64
#define GSTR_B   144                 // 128B data + 16B pad
#define GTILE_B  (128*GSTR_B)        // 18432
#define GSTAGE_B (2*GTILE_B)         // 36864

__device__ __forceinline__ void gemm_load(uint32_t sdst, int tid, int k0, int m0, int n0)
{
#pragma unroll
    for (int i = 0; i < 16; i++) {
        const int tile = i >> 3;                 // 0 xh, 1 wh
        int idx = ((i & 7) << 7) + tid;          // 0..1023
        int row = idx >> 3, q = idx & 7;
        const __half* g =
            (tile == 0) ? g_xh + (size_t)(m0 + row) * CDIM :
                          g_wh + (size_t)(n0 + row) * CDIM;
        CP_ASYNC(sdst + tile * GTILE_B + row * GSTR_B + q * 16, g + k0 + q * 8);
    }
}

__global__ __launch_bounds__(128, 3) void qkv_gemm_mma(const float* __restrict__ bias)
{
    extern __shared__ char smg[];
    const uint32_t sbase = smem_to_u32(smg);
    const int tid = threadIdx.x, lane = tid & 31, wid = tid >> 5;
    const int m0 = blockIdx.y * 128, n0 = blockIdx.x * 128;
    const int wm = wid & 1, wn = wid >> 1;

    float acc[4][8][4];
#pragma unroll
    for (int mi = 0; mi < 4; mi++)
#pragma unroll
        for (int nj = 0; nj < 8; nj++)
#pragma unroll
            for (int c = 0; c < 4; c++) acc[mi][nj][c] = 0.f;

    gemm_load(sbase, tid, 0, m0, n0);
    CP_COMMIT();

    const int NCH = CDIM / KCG;     // 16
    for (int c = 0; c < NCH; c++) {
        const int buf = c & 1;
        if (c + 1 < NCH) {
            gemm_load(sbase + (buf ^ 1) * GSTAGE_B, tid, (c + 1) * KCG, m0, n0);
            CP_COMMIT();
            CP_WAIT1();
        } else {
            CP_WAIT0();
        }
        __syncthreads();

        const uint32_t bb = sbase + buf * GSTAGE_B;
#pragma unroll
        for (int ks = 0; ks < 4; ks++) {
            const uint32_t coff = (ks * 16 + ((lane >> 4) << 3)) * 2;
            uint32_t ah[4][4];
#pragma unroll
            for (int mi = 0; mi < 4; mi++) {
                uint32_t ra = bb + (wm * 64 + mi * 16 + (lane & 15)) * GSTR_B + coff;
                ldsm4(ah[mi], ra);
            }
#pragma unroll
            for (int g2 = 0; g2 < 4; g2++) {
                uint32_t bh4[4];
                uint32_t rb = bb + GTILE_B +
                              (wn * 64 + g2 * 16 + (lane & 15)) * GSTR_B + coff;
                ldsm4(bh4, rb);
#pragma unroll
                for (int mi = 0; mi < 4; mi++) {
                    mma_f16(acc[mi][2*g2],   ah[mi], bh4[0], bh4[2]);
                    mma_f16(acc[mi][2*g2+1], ah[mi], bh4[1], bh4[3]);
                }
            }
        }
        __syncthreads();
    }

    // epilogue: +bias; Q scaled; all regions -> fp16
    const int nb = n0 + wn * 64;
    const int region = nb >> 10;
    const int h = (nb & 1023) >> 6;
    __half* dh = region == 0 ? g_qh : region == 1 ? g_kh : g_vh;
    const float scale = (region == 0) ? QSCALE : 1.0f;

#pragma unroll
    for (int mi = 0; mi < 4; mi++) {
#pragma unroll
        for (int rr = 0; rr < 2; rr++) {
            const int m = m0 + wm * 64 + mi * 16 + (lane >> 2) + rr * 8;
            const int b = m >> 11, t = m & 2047;
            const size_t roff = (((size_t)b * HEADS + h) * TSEQ + t) * HD;
#pragma unroll
            for (int nj = 0; nj < 8; nj++) {
                const int d = nj * 8 + 2 * (lane & 3);
                float2 bv = *(const float2*)(bias + nb + d);
                float v0 = (acc[mi][nj][rr*2+0] + bv.x) * scale;
                float v1 = (acc[mi][nj][rr*2+1] + bv.y) * scale;
                *(__half2*)(dh + roff + d) =
                    __half2(__float2half(v0), __float2half(v1));
            }
        }
    }
}

// ---------------------------------------------------------------------------
// Kernel 2: flash attention, fp16 mma.sync (fp32 accum), 2 CTAs/SM.
// 3-stage KV ring, single sync/iter. Prefetch issued AFTER the sync (fixes
// the R12 race); tail uses WAIT0 (fixes empty-group wait bug).
// ---------------------------------------------------------------------------
#define ASTR_B   144                // 64 fp16 (128B) + 16B pad
#define QTILE_B  (128*ASTR_B)       // 18432
#define KTILE_B  (64*ASTR_B)        // 9216
#define ABUF0    QTILE_B            // 18432
#define ABUF_B   (2*KTILE_B)        // 18432 (kh, vh)
#define NSTAGE   3

__device__ __forceinline__ void kv_load(uint32_t sbase, int tid, size_t krow0,
                                        int kb, int buf)
{
#pragma unroll
    for (int i = 0; i < 4; i++) {
        const int arr = i >> 1;                // 0 kh, 1 vh
        int rem = ((i & 1) << 8) + tid;        // 0..511
        int row = rem >> 3, q = rem & 7;
        const __half* g = (arr == 0 ? g_kh : g_vh) +
                          (krow0 + (size_t)kb * 64 + row) * HD + q * 8;
        CP_ASYNC(sbase + ABUF0 + buf * ABUF_B + arr * KTILE_B + row * ASTR_B + q * 16, g);
    }
}

__global__ __launch_bounds__(256, 2) void attn_mma(float* __restrict__ out)
{
    extern __shared__ char sma[];
    const uint32_t sbase = smem_to_u32(sma);
    const int tid = threadIdx.x, lane = tid & 31, wid = tid >> 5;
    const int qbi = gridDim.x - 1 - blockIdx.x;
    const int bh = blockIdx.y;
    const int kmax = 2 * qbi + 2;
    const size_t qrow0 = (size_t)bh * TSEQ + (size_t)qbi * 128;
    const size_t krow0 = (size_t)bh * TSEQ;

    // Q (fp16, pre-scaled) -> smem;  prime KV stages 0 and 1
#pragma unroll
    for (int i = 0; i < 4; i++) {
        int rem = (i << 8) + tid;               // 0..1023
        int row = rem >> 3, q = rem & 7;
        const __half* g = g_qh + (qrow0 + row) * HD + q * 8;
        CP_ASYNC(sbase + row * ASTR_B + q * 16, g);
    }
    kv_load(sbase, tid, krow0, 0, 0);
    CP_COMMIT();                                 // G(Q + kv0)
    kv_load(sbase, tid, krow0, 1, 1);            // kmax >= 2 always
    CP_COMMIT();                                 // G(kv1)
    CP_WAIT1();                                  // Q + kv0 arrived
    __syncthreads();

    uint32_t qfh[4][4];
#pragma unroll
    for (int ks = 0; ks < 4; ks++) {
        uint32_t a = sbase + (wid * 16 + (lane & 15)) * ASTR_B +
                     (ks * 16 + ((lane >> 4) << 3)) * 2;
        ldsm4(qfh[ks], a);
    }

    float o[8][4];
#pragma unroll
    for (int nj = 0; nj < 8; nj++)
#pragma unroll
        for (int c = 0; c < 4; c++) o[nj][c] = 0.f;
    float m1 = -1e30f, m2 = -1e30f, l1 = 0.f, l2 = 0.f;

    int buf = 0;
    for (int kb = 0; kb < kmax; kb++) {
        if (kb > 0) {
            // wait for stage kb. If a real newer group (kv for kb+1) exists,
            // WAIT1 suffices; otherwise drain everything (tail).
            if (kb + 1 < kmax) { CP_WAIT1(); } else { CP_WAIT0(); }
            __syncthreads();     // all warps done reading stage kb-1, see stage kb
        }
        // prefetch kb+2 AFTER the sync: the target stage's readers (iter kb-1)
        // have all passed the barrier above (or the prologue barrier for kb=0,
        // where the target stage 2 was never yet used).
        if (kb + 2 < kmax) {
            int nbuf = buf + 2; if (nbuf >= NSTAGE) nbuf -= NSTAGE;
            kv_load(sbase, tid, krow0, kb + 2, nbuf);
            CP_COMMIT();
        }

        const bool active = (kb * 64 <= qbi * 128 + wid * 16 + 15);
        if (active) {
            // ---- S = qh * kh: 4-acc interleave ----
            float s[8][4];
#pragma unroll
            for (int nj = 0; nj < 8; nj++)
#pragma unroll
                for (int c = 0; c < 4; c++) s[nj][c] = 0.f;

            const uint32_t kbase = sbase + ABUF0 + buf * ABUF_B;
#pragma unroll
            for (int ks = 0; ks < 4; ks++) {
                const uint32_t coff = (ks * 16 + ((lane >> 4) << 3)) * 2;
#pragma unroll
                for (int gp = 0; gp < 2; gp++) {
                    uint32_t ka[4], kb4[4];
                    uint32_t ra = kbase + (gp * 32 + (lane & 15)) * ASTR_B + coff;
                    uint32_t rb = ra + 16 * ASTR_B;
                    ldsm4(ka,  ra);
                    ldsm4(kb4, rb);
                    mma_f16(s[4*gp+0], qfh[ks], ka[0],  ka[2]);
                    mma_f16(s[4*gp+1], qfh[ks], ka[1],  ka[3]);
                    mma_f16(s[4*gp+2], qfh[ks], kb4[0], kb4[2]);
                    mma_f16(s[4*gp+3], qfh[ks], kb4[1], kb4[3]);
                }
            }

            // ---- causal mask (diagonal band) ----
            if (kb >= 2 * qbi) {
                const int q1 = qbi * 128 + wid * 16 + (lane >> 2);
                const int tb = kb * 64 + 2 * (lane & 3);
#pragma unroll
                for (int nj = 0; nj < 8; nj++) {
                    const int t0 = tb + 8 * nj;
                    if (t0     > q1)     s[nj][0] = -1e30f;
                    if (t0 + 1 > q1)     s[nj][1] = -1e30f;
                    if (t0     > q1 + 8) s[nj][2] = -1e30f;
                    if (t0 + 1 > q1 + 8) s[nj][3] = -1e30f;
                }
            }

            // ---- online softmax, base-2 ----
            float mx1 = -1e30f, mx2 = -1e30f;
#pragma unroll
            for (int nj = 0; nj < 8; nj++) {
                mx1 = fmaxf(mx1, fmaxf(s[nj][0], s[nj][1]));
                mx2 = fmaxf(mx2, fmaxf(s[nj][2], s[nj][3]));
            }
            mx1 = fmaxf(mx1, __shfl_xor_sync(0xffffffffu, mx1, 1));
            mx1 = fmaxf(mx1, __shfl_xor_sync(0xffffffffu, mx1, 2));
            mx2 = fmaxf(mx2, __shfl_xor_sync(0xffffffffu, mx2, 1));
            mx2 = fmaxf(mx2, __shfl_xor_sync(0xffffffffu, mx2, 2));
            const float mn1 = fmaxf(m1, mx1), mn2 = fmaxf(m2, mx2);
            const float a1 = exp2f(m1 - mn1), a2 = exp2f(m2 - mn2);
            float rs1 = 0.f, rs2 = 0.f;
#pragma unroll
            for (int nj = 0; nj < 8; nj++) {
                s[nj][0] = exp2f(s[nj][0] - mn1);
                s[nj][1] = exp2f(s[nj][1] - mn1);
                s[nj][2] = exp2f(s[nj][2] - mn2);
                s[nj][3] = exp2f(s[nj][3] - mn2);
                rs1 += s[nj][0] + s[nj][1];
                rs2 += s[nj][2] + s[nj][3];
            }
            rs1 += __shfl_xor_sync(0xffffffffu, rs1, 1);
            rs1 += __shfl_xor_sync(0xffffffffu, rs1, 2);
            rs2 += __shfl_xor_sync(0xffffffffu, rs2, 1);
            rs2 += __shfl_xor_sync(0xffffffffu, rs2, 2);
            l1 = l1 * a1 + rs1;  l2 = l2 * a2 + rs2;
            m1 = mn1;            m2 = mn2;
#pragma unroll
            for (int nj = 0; nj < 8; nj++) {
                o[nj][0] *= a1; o[nj][1] *= a1;
                o[nj][2] *= a2; o[nj][3] *= a2;
            }

            // ---- O += P V (single fp16 MMA, 8-acc interleave) ----
            const uint32_t vbase = kbase + KTILE_B;
#pragma unroll
            for (int kt = 0; kt < 4; kt++) {
                uint32_t ph[4];
                {
                    const float* p0 = s[2 * kt];
                    const float* p1 = s[2 * kt + 1];
                    ph[0] = pack2h(__float2half(p0[0]), __float2half(p0[1]));
                    ph[1] = pack2h(__float2half(p0[2]), __float2half(p0[3]));
                    ph[2] = pack2h(__float2half(p1[0]), __float2half(p1[1]));
                    ph[3] = pack2h(__float2half(p1[2]), __float2half(p1[3]));
                }
#pragma unroll
                for (int g2 = 0; g2 < 4; g2++) {
                    uint32_t vh4[4];
                    uint32_t rb = vbase + (kt * 16 + (lane & 15)) * ASTR_B +
                                  (g2 * 16 + ((lane >> 4) << 3)) * 2;
                    ldsm4t(vh4, rb);
                    mma_f16(o[2*g2],   ph, vh4[0], vh4[1]);
                    mma_f16(o[2*g2+1], ph, vh4[2], vh4[3]);
                }
            }
        }
        if (++buf == NSTAGE) buf = 0;
    }

    // epilogue
    const float inv1 = 1.f / l1, inv2 = 1.f / l2;
    const int b = bh >> 4, h = bh & 15;
    const int t1 = qbi * 128 + wid * 16 + (lane >> 2);
    float* o1p = out + ((size_t)b * TSEQ + t1) * CDIM + h * 64 + 2 * (lane & 3);
    float* o2p = o1p + (size_t)8 * CDIM;
#pragma unroll
    for (int nj = 0; nj < 8; nj++) {
        *(float2*)(o1p + 8 * nj) = make_float2(o[nj][0] * inv1, o[nj][1] * inv1);
        *(float2*)(o2p + 8 * nj) = make_float2(o[nj][2] * inv2, o[nj][3] * inv2);
    }
}

// ---------------------------------------------------------------------------
extern "C" void kernel_launch(void* const* d_in, const int* in_sizes, int n_in,
                              void* d_out, int out_size)
{
    (void)in_sizes; (void)n_in; (void)out_size;
    const float* x  = (const float*)d_in[0];
    const float* w  = (const float*)d_in[1];
    const float* bb = (const float*)d_in[2];
    float* out = (float*)d_out;

    const int nx4 = BT * CDIM / 4;
    const int nw4 = NQKV * CDIM / 4;
    conv_all<<<(nx4 + nw4 + 255) / 256, 256>>>(x, w, nx4, nw4);

    const int gsmem = 2 * GSTAGE_B;                     // 73728
    cudaFuncSetAttribute((const void*)qkv_gemm_mma,
                         cudaFuncAttributeMaxDynamicSharedMemorySize, gsmem);
    dim3 gg(NQKV / 128, BT / 128);                      // (24, 64)
    qkv_gemm_mma<<<gg, 128, gsmem>>>(bb);

    const int asmem = ABUF0 + NSTAGE * ABUF_B;          // 73728
    cudaFuncSetAttribute((const void*)attn_mma,
                         cudaFuncAttributeMaxDynamicSharedMemorySize, asmem);
    dim3 ga(TSEQ / 128, NB * HEADS);                    // (16, 64)
    attn_mma<<<ga, 256, asmem>>>(out);
}

// round 14
// speedup vs baseline: 1.0046x; 1.0046x over previous
#include <cuda_runtime.h>
#include <cuda_fp16.h>
#include <cstdint>

#define NB    4
#define TSEQ  2048
#define CDIM  1024
#define HEADS 16
#define HD    64
#define BT    (NB*TSEQ)          // 8192
#define NQKV  3072

// Q pre-scale: 1/sqrt(64) * log2(e)  (softmax in base-2 domain)
#define QSCALE (0.125f * 1.44269504088896f)

// ---------------------------------------------------------------------------
// __device__ global scratch
// ---------------------------------------------------------------------------
__device__ __half g_xh[(size_t)BT*CDIM];
__device__ __half g_wh[(size_t)NQKV*CDIM];
// Q fp16 (scaled), K fp16, V fp16 — all [B,H,T,D]
__device__ __half g_qh[(size_t)NB*HEADS*TSEQ*HD];
__device__ __half g_kh[(size_t)NB*HEADS*TSEQ*HD];
__device__ __half g_vh[(size_t)NB*HEADS*TSEQ*HD];

// ---------------------------------------------------------------------------
// Helpers
// ---------------------------------------------------------------------------
__device__ __forceinline__ uint32_t smem_to_u32(const void* p) {
    uint32_t a;
    asm("{ .reg .u64 t; cvta.to.shared.u64 t, %1; cvt.u32.u64 %0, t; }" : "=r"(a) : "l"(p));
    return a;
}
#define CP_ASYNC(dst, src) \
    asm volatile("cp.async.cg.shared.global [%0], [%1], 16;\n" :: "r"(dst), "l"(src))
#define CP_COMMIT() asm volatile("cp.async.commit_group;\n" ::: "memory")
#define CP_WAIT1()  asm volatile("cp.async.wait_group 1;\n" ::: "memory")
#define CP_WAIT0()  asm volatile("cp.async.wait_group 0;\n" ::: "memory")

__device__ __forceinline__ void ldsm4(uint32_t r[4], uint32_t a) {
    asm volatile("ldmatrix.sync.aligned.m8n8.x4.shared.b16 {%0,%1,%2,%3}, [%4];"
                 : "=r"(r[0]), "=r"(r[1]), "=r"(r[2]), "=r"(r[3]) : "r"(a));
}
__device__ __forceinline__ void ldsm4t(uint32_t r[4], uint32_t a) {
    asm volatile("ldmatrix.sync.aligned.m8n8.x4.trans.shared.b16 {%0,%1,%2,%3}, [%4];"
                 : "=r"(r[0]), "=r"(r[1]), "=r"(r[2]), "=r"(r[3]) : "r"(a));
}
__device__ __forceinline__ void mma_f16(float c[4], const uint32_t a[4],
                                        uint32_t b0, uint32_t b1) {
    asm volatile("mma.sync.aligned.m16n8k16.row.col.f32.f16.f16.f32 "
                 "{%0,%1,%2,%3}, {%4,%5,%6,%7}, {%8,%9}, {%0,%1,%2,%3};"
                 : "+f"(c[0]), "+f"(c[1]), "+f"(c[2]), "+f"(c[3])
                 : "r"(a[0]), "r"(a[1]), "r"(a[2]), "r"(a[3]), "r"(b0), "r"(b1));
}
__device__ __forceinline__ uint32_t pack2h(__half a, __half b) {
    __half2 t(a, b);
    return *reinterpret_cast<uint32_t*>(&t);
}

// ---------------------------------------------------------------------------
// Kernel 0: fused fp32 -> fp16 convert; 2 float4/thread, block-contiguous
// (each block covers 512 consecutive float4s; both accesses coalesced)
// ---------------------------------------------------------------------------
__global__ __launch_bounds__(256) void conv_all(const float* __restrict__ x,
                                                const float* __restrict__ w,
                                                int nx4, int nw4)
{
    const int b0 = blockIdx.x * 512 + threadIdx.x;
#pragma unroll
    for (int u = 0; u < 2; u++) {
        int i = b0 + u * 256;
        const float* src;
        __half2* dp;
        int j;
        if (i < nx4) {
            src = x; dp = (__half2*)g_xh; j = i;
        } else {
            j = i - nx4;
            if (j >= nw4) continue;
            src = w; dp = (__half2*)g_wh;
        }
        float4 v = ((const float4*)src)[j];
        dp[2*j]   = __half2(__float2half(v.x), __float2half(v.y));
        dp[2*j+1] = __half2(__float2half(v.z), __float2half(v.w));
    }
}

// ---------------------------------------------------------------------------
// Kernel 1: QKV GEMM = xh * wh, single fp16 MMA (fp32 accum) per product.
// CTA 128x128, 4 warps (64x64), KC=64 double-buffered, 3 CTAs/SM. (R11 form)
// ---------------------------------------------------------------------------
#define KCG      64
#define GSTR_B   144                 // 128B data + 16B pad
#define GTILE_B  (128*GSTR_B)        // 18432
#define GSTAGE_B (2*GTILE_B)         // 36864

__device__ __forceinline__ void gemm_load(uint32_t sdst, int tid, int k0, int m0, int n0)
{
#pragma unroll
    for (int i = 0; i < 16; i++) {
        const int tile = i >> 3;                 // 0 xh, 1 wh
        int idx = ((i & 7) << 7) + tid;          // 0..1023
        int row = idx >> 3, q = idx & 7;
        const __half* g =
            (tile == 0) ? g_xh + (size_t)(m0 + row) * CDIM :
                          g_wh + (size_t)(n0 + row) * CDIM;
        CP_ASYNC(sdst + tile * GTILE_B + row * GSTR_B + q * 16, g + k0 + q * 8);
    }
}

__global__ __launch_bounds__(128, 3) void qkv_gemm_mma(const float* __restrict__ bias)
{
    extern __shared__ char smg[];
    const uint32_t sbase = smem_to_u32(smg);
    const int tid = threadIdx.x, lane = tid & 31, wid = tid >> 5;
    const int m0 = blockIdx.y * 128, n0 = blockIdx.x * 128;
    const int wm = wid & 1, wn = wid >> 1;

    float acc[4][8][4];
#pragma unroll
    for (int mi = 0; mi < 4; mi++)
#pragma unroll
        for (int nj = 0; nj < 8; nj++)
#pragma unroll
            for (int c = 0; c < 4; c++) acc[mi][nj][c] = 0.f;

    gemm_load(sbase, tid, 0, m0, n0);
    CP_COMMIT();

    const int NCH = CDIM / KCG;     // 16
    for (int c = 0; c < NCH; c++) {
        const int buf = c & 1;
        if (c + 1 < NCH) {
            gemm_load(sbase + (buf ^ 1) * GSTAGE_B, tid, (c + 1) * KCG, m0, n0);
            CP_COMMIT();
            CP_WAIT1();
        } else {
            CP_WAIT0();
        }
        __syncthreads();

        const uint32_t bb = sbase + buf * GSTAGE_B;
#pragma unroll
        for (int ks = 0; ks < 4; ks++) {
            const uint32_t coff = (ks * 16 + ((lane >> 4) << 3)) * 2;
            uint32_t ah[4][4];
#pragma unroll
            for (int mi = 0; mi < 4; mi++) {
                uint32_t ra = bb + (wm * 64 + mi * 16 + (lane & 15)) * GSTR_B + coff;
                ldsm4(ah[mi], ra);
            }
#pragma unroll
            for (int g2 = 0; g2 < 4; g2++) {
                uint32_t bh4[4];
                uint32_t rb = bb + GTILE_B +
                              (wn * 64 + g2 * 16 + (lane & 15)) * GSTR_B + coff;
                ldsm4(bh4, rb);
#pragma unroll
                for (int mi = 0; mi < 4; mi++) {
                    mma_f16(acc[mi][2*g2],   ah[mi], bh4[0], bh4[2]);
                    mma_f16(acc[mi][2*g2+1], ah[mi], bh4[1], bh4[3]);
                }
            }
        }
        __syncthreads();
    }

    // epilogue: +bias; Q scaled; all regions -> fp16
    const int nb = n0 + wn * 64;
    const int region = nb >> 10;
    const int h = (nb & 1023) >> 6;
    __half* dh = region == 0 ? g_qh : region == 1 ? g_kh : g_vh;
    const float scale = (region == 0) ? QSCALE : 1.0f;

#pragma unroll
    for (int mi = 0; mi < 4; mi++) {
#pragma unroll
        for (int rr = 0; rr < 2; rr++) {
            const int m = m0 + wm * 64 + mi * 16 + (lane >> 2) + rr * 8;
            const int b = m >> 11, t = m & 2047;
            const size_t roff = (((size_t)b * HEADS + h) * TSEQ + t) * HD;
#pragma unroll
            for (int nj = 0; nj < 8; nj++) {
                const int d = nj * 8 + 2 * (lane & 3);
                float2 bv = *(const float2*)(bias + nb + d);
                float v0 = (acc[mi][nj][rr*2+0] + bv.x) * scale;
                float v1 = (acc[mi][nj][rr*2+1] + bv.y) * scale;
                *(__half2*)(dh + roff + d) =
                    __half2(__float2half(v0), __float2half(v1));
            }
        }
    }
}

// ---------------------------------------------------------------------------
// Kernel 2: flash attention, fp16 mma.sync (fp32 accum), 2 CTAs/SM.
// S = qh*kh (1 MMA); P*V single fp16 MMA. 2-buffer loop (R10 proven form).
// ---------------------------------------------------------------------------
#define ASTR_B   144                // 64 fp16 (128B) + 16B pad
#define QTILE_B  (128*ASTR_B)       // 18432
#define KTILE_B  (64*ASTR_B)        // 9216
#define ABUF0    QTILE_B            // 18432
#define ABUF_B   (2*KTILE_B)        // 18432 (kh, vh)

__device__ __forceinline__ void kv_load(uint32_t sbase, int tid, size_t krow0,
                                        int kb, int buf)
{
#pragma unroll
    for (int i = 0; i < 4; i++) {
        const int arr = i >> 1;                // 0 kh, 1 vh
        int rem = ((i & 1) << 8) + tid;        // 0..511
        int row = rem >> 3, q = rem & 7;
        const __half* g = (arr == 0 ? g_kh : g_vh) +
                          (krow0 + (size_t)kb * 64 + row) * HD + q * 8;
        CP_ASYNC(sbase + ABUF0 + buf * ABUF_B + arr * KTILE_B + row * ASTR_B + q * 16, g);
    }
}

__global__ __launch_bounds__(256, 2) void attn_mma(float* __restrict__ out)
{
    extern __shared__ char sma[];
    const uint32_t sbase = smem_to_u32(sma);
    const int tid = threadIdx.x, lane = tid & 31, wid = tid >> 5;
    const int qbi = gridDim.x - 1 - blockIdx.x;
    const int bh = blockIdx.y;
    const int kmax = 2 * qbi + 2;
    const size_t qrow0 = (size_t)bh * TSEQ + (size_t)qbi * 128;
    const size_t krow0 = (size_t)bh * TSEQ;

    // Q (fp16, pre-scaled) -> smem
#pragma unroll
    for (int i = 0; i < 4; i++) {
        int rem = (i << 8) + tid;               // 0..1023
        int row = rem >> 3, q = rem & 7;
        const __half* g = g_qh + (qrow0 + row) * HD + q * 8;
        CP_ASYNC(sbase + row * ASTR_B + q * 16, g);
    }
    CP_COMMIT();
    kv_load(sbase, tid, krow0, 0, 0);
    CP_COMMIT();
    CP_WAIT1();
    __syncthreads();

    uint32_t qfh[4][4];
#pragma unroll
    for (int ks = 0; ks < 4; ks++) {
        uint32_t a = sbase + (wid * 16 + (lane & 15)) * ASTR_B +
                     (ks * 16 + ((lane >> 4) << 3)) * 2;
        ldsm4(qfh[ks], a);
    }

    float o[8][4];
#pragma unroll
    for (int nj = 0; nj < 8; nj++)
#pragma unroll
        for (int c = 0; c < 4; c++) o[nj][c] = 0.f;
    float m1 = -1e30f, m2 = -1e30f, l1 = 0.f, l2 = 0.f;

    for (int kb = 0; kb < kmax; kb++) {
        const int buf = kb & 1;
        if (kb + 1 < kmax) {
            kv_load(sbase, tid, krow0, kb + 1, buf ^ 1);
            CP_COMMIT();
            CP_WAIT1();
        } else {
            CP_WAIT0();
        }
        __syncthreads();

        const bool active = (kb * 64 <= qbi * 128 + wid * 16 + 15);
        if (active) {
            // ---- S = qh * kh: 4-acc interleave ----
            float s[8][4];
#pragma unroll
            for (int nj = 0; nj < 8; nj++)
#pragma unroll
                for (int c = 0; c < 4; c++) s[nj][c] = 0.f;

            const uint32_t kbase = sbase + ABUF0 + buf * ABUF_B;
#pragma unroll
            for (int ks = 0; ks < 4; ks++) {
                const uint32_t coff = (ks * 16 + ((lane >> 4) << 3)) * 2;
#pragma unroll
                for (int gp = 0; gp < 2; gp++) {
                    uint32_t ka[4], kb4[4];
                    uint32_t ra = kbase + (gp * 32 + (lane & 15)) * ASTR_B + coff;
                    uint32_t rb = ra + 16 * ASTR_B;
                    ldsm4(ka,  ra);
                    ldsm4(kb4, rb);
                    mma_f16(s[4*gp+0], qfh[ks], ka[0],  ka[2]);
                    mma_f16(s[4*gp+1], qfh[ks], ka[1],  ka[3]);
                    mma_f16(s[4*gp+2], qfh[ks], kb4[0], kb4[2]);
                    mma_f16(s[4*gp+3], qfh[ks], kb4[1], kb4[3]);
                }
            }

            // ---- causal mask (diagonal band) ----
            if (kb >= 2 * qbi) {
                const int q1 = qbi * 128 + wid * 16 + (lane >> 2);
                const int tb = kb * 64 + 2 * (lane & 3);
#pragma unroll
                for (int nj = 0; nj < 8; nj++) {
                    const int t0 = tb + 8 * nj;
                    if (t0     > q1)     s[nj][0] = -1e30f;
                    if (t0 + 1 > q1)     s[nj][1] = -1e30f;
                    if (t0     > q1 + 8) s[nj][2] = -1e30f;
                    if (t0 + 1 > q1 + 8) s[nj][3] = -1e30f;
                }
            }

            // ---- online softmax, base-2 ----
            float mx1 = -1e30f, mx2 = -1e30f;
#pragma unroll
            for (int nj = 0; nj < 8; nj++) {
                mx1 = fmaxf(mx1, fmaxf(s[nj][0], s[nj][1]));
                mx2 = fmaxf(mx2, fmaxf(s[nj][2], s[nj][3]));
            }
            mx1 = fmaxf(mx1, __shfl_xor_sync(0xffffffffu, mx1, 1));
            mx1 = fmaxf(mx1, __shfl_xor_sync(0xffffffffu, mx1, 2));
            mx2 = fmaxf(mx2, __shfl_xor_sync(0xffffffffu, mx2, 1));
            mx2 = fmaxf(mx2, __shfl_xor_sync(0xffffffffu, mx2, 2));
            const float mn1 = fmaxf(m1, mx1), mn2 = fmaxf(m2, mx2);
            const float a1 = exp2f(m1 - mn1), a2 = exp2f(m2 - mn2);
            float rs1 = 0.f, rs2 = 0.f;
#pragma unroll
            for (int nj = 0; nj < 8; nj++) {
                s[nj][0] = exp2f(s[nj][0] - mn1);
                s[nj][1] = exp2f(s[nj][1] - mn1);
                s[nj][2] = exp2f(s[nj][2] - mn2);
                s[nj][3] = exp2f(s[nj][3] - mn2);
                rs1 += s[nj][0] + s[nj][1];
                rs2 += s[nj][2] + s[nj][3];
            }
            rs1 += __shfl_xor_sync(0xffffffffu, rs1, 1);
            rs1 += __shfl_xor_sync(0xffffffffu, rs1, 2);
            rs2 += __shfl_xor_sync(0xffffffffu, rs2, 1);
            rs2 += __shfl_xor_sync(0xffffffffu, rs2, 2);
            l1 = l1 * a1 + rs1;  l2 = l2 * a2 + rs2;
            m1 = mn1;            m2 = mn2;
#pragma unroll
            for (int nj = 0; nj < 8; nj++) {
                o[nj][0] *= a1; o[nj][1] *= a1;
                o[nj][2] *= a2; o[nj][3] *= a2;
            }

            // ---- O += P V (single fp16 MMA, 8-acc interleave) ----
            const uint32_t vbase = kbase + KTILE_B;
#pragma unroll
            for (int kt = 0; kt < 4; kt++) {
                uint32_t ph[4];
                {
                    const float* p0 = s[2 * kt];
                    const float* p1 = s[2 * kt + 1];
                    ph[0] = pack2h(__float2half(p0[0]), __float2half(p0[1]));
                    ph[1] = pack2h(__float2half(p0[2]), __float2half(p0[3]));
                    ph[2] = pack2h(__float2half(p1[0]), __float2half(p1[1]));
                    ph[3] = pack2h(__float2half(p1[2]), __float2half(p1[3]));
                }
#pragma unroll
                for (int g2 = 0; g2 < 4; g2++) {
                    uint32_t vh4[4];
                    uint32_t rb = vbase + (kt * 16 + (lane & 15)) * ASTR_B +
                                  (g2 * 16 + ((lane >> 4) << 3)) * 2;
                    ldsm4t(vh4, rb);
                    mma_f16(o[2*g2],   ph, vh4[0], vh4[1]);
                    mma_f16(o[2*g2+1], ph, vh4[2], vh4[3]);
                }
            }
        }
        __syncthreads();
    }

    // epilogue
    const float inv1 = 1.f / l1, inv2 = 1.f / l2;
    const int b = bh >> 4, h = bh & 15;
    const int t1 = qbi * 128 + wid * 16 + (lane >> 2);
    float* o1p = out + ((size_t)b * TSEQ + t1) * CDIM + h * 64 + 2 * (lane & 3);
    float* o2p = o1p + (size_t)8 * CDIM;
#pragma unroll
    for (int nj = 0; nj < 8; nj++) {
        *(float2*)(o1p + 8 * nj) = make_float2(o[nj][0] * inv1, o[nj][1] * inv1);
        *(float2*)(o2p + 8 * nj) = make_float2(o[nj][2] * inv2, o[nj][3] * inv2);
    }
}

// ---------------------------------------------------------------------------
extern "C" void kernel_launch(void* const* d_in, const int* in_sizes, int n_in,
                              void* d_out, int out_size)
{
    (void)in_sizes; (void)n_in; (void)out_size;
    const float* x  = (const float*)d_in[0];
    const float* w  = (const float*)d_in[1];
    const float* bb = (const float*)d_in[2];
    float* out = (float*)d_out;

    const int nx4 = BT * CDIM / 4;
    const int nw4 = NQKV * CDIM / 4;
    const int ntot = nx4 + nw4;
    conv_all<<<(ntot + 511) / 512, 256>>>(x, w, nx4, nw4);

    const int gsmem = 2 * GSTAGE_B;                     // 73728
    cudaFuncSetAttribute((const void*)qkv_gemm_mma,
                         cudaFuncAttributeMaxDynamicSharedMemorySize, gsmem);
    dim3 gg(NQKV / 128, BT / 128);                      // (24, 64)
    qkv_gemm_mma<<<gg, 128, gsmem>>>(bb);

    const int asmem = ABUF0 + 2 * ABUF_B;               // 55296
    cudaFuncSetAttribute((const void*)attn_mma,
                         cudaFuncAttributeMaxDynamicSharedMemorySize, asmem);
    dim3 ga(TSEQ / 128, NB * HEADS);                    // (16, 64)
    attn_mma<<<ga, 256, asmem>>>(out);
}

// round 15
// speedup vs baseline: 1.0182x; 1.0136x over previous
#include <cuda_runtime.h>
#include <cuda_fp16.h>
#include <cstdint>

#define NB    4
#define TSEQ  2048
#define CDIM  1024
#define HEADS 16
#define HD    64
#define BT    (NB*TSEQ)          // 8192
#define NQKV  3072

// Q pre-scale: 1/sqrt(64) * log2(e)  (softmax in base-2 domain)
#define QSCALE (0.125f * 1.44269504088896f)

// ---------------------------------------------------------------------------
// __device__ global scratch
// ---------------------------------------------------------------------------
__device__ __half g_xh[(size_t)BT*CDIM];
__device__ __half g_wh[(size_t)NQKV*CDIM];
// Q fp16 (scaled), K fp16, V fp16 — all [B,H,T,D]
__device__ __half g_qh[(size_t)NB*HEADS*TSEQ*HD];
__device__ __half g_kh[(size_t)NB*HEADS*TSEQ*HD];
__device__ __half g_vh[(size_t)NB*HEADS*TSEQ*HD];

// ---------------------------------------------------------------------------
// Helpers
// ---------------------------------------------------------------------------
__device__ __forceinline__ uint32_t smem_to_u32(const void* p) {
    uint32_t a;
    asm("{ .reg .u64 t; cvta.to.shared.u64 t, %1; cvt.u32.u64 %0, t; }" : "=r"(a) : "l"(p));
    return a;
}
#define CP_ASYNC(dst, src) \
    asm volatile("cp.async.cg.shared.global [%0], [%1], 16;\n" :: "r"(dst), "l"(src))
#define CP_COMMIT() asm volatile("cp.async.commit_group;\n" ::: "memory")
#define CP_WAIT1()  asm volatile("cp.async.wait_group 1;\n" ::: "memory")
#define CP_WAIT0()  asm volatile("cp.async.wait_group 0;\n" ::: "memory")

__device__ __forceinline__ void ldsm4(uint32_t r[4], uint32_t a) {
    asm volatile("ldmatrix.sync.aligned.m8n8.x4.shared.b16 {%0,%1,%2,%3}, [%4];"
                 : "=r"(r[0]), "=r"(r[1]), "=r"(r[2]), "=r"(r[3]) : "r"(a));
}
__device__ __forceinline__ void ldsm4t(uint32_t r[4], uint32_t a) {
    asm volatile("ldmatrix.sync.aligned.m8n8.x4.trans.shared.b16 {%0,%1,%2,%3}, [%4];"
                 : "=r"(r[0]), "=r"(r[1]), "=r"(r[2]), "=r"(r[3]) : "r"(a));
}
__device__ __forceinline__ void mma_f16(float c[4], const uint32_t a[4],
                                        uint32_t b0, uint32_t b1) {
    asm volatile("mma.sync.aligned.m16n8k16.row.col.f32.f16.f16.f32 "
                 "{%0,%1,%2,%3}, {%4,%5,%6,%7}, {%8,%9}, {%0,%1,%2,%3};"
                 : "+f"(c[0]), "+f"(c[1]), "+f"(c[2]), "+f"(c[3])
                 : "r"(a[0]), "r"(a[1]), "r"(a[2]), "r"(a[3]), "r"(b0), "r"(b1));
}
__device__ __forceinline__ uint32_t pack2h(__half a, __half b) {
    __half2 t(a, b);
    return *reinterpret_cast<uint32_t*>(&t);
}

// ---------------------------------------------------------------------------
// Kernel 0: fused fp32 -> fp16 convert (coalesced, 1 float4/thread)
// ---------------------------------------------------------------------------
__global__ __launch_bounds__(256) void conv_all(const float* __restrict__ x,
                                                const float* __restrict__ w,
                                                int nx4, int nw4)
{
    int i = blockIdx.x * 256 + threadIdx.x;
    const float* src;
    __half2* dp;
    int j;
    if (i < nx4) {
        src = x; dp = (__half2*)g_xh; j = i;
    } else {
        j = i - nx4;
        if (j >= nw4) return;
        src = w; dp = (__half2*)g_wh;
    }
    float4 v = ((const float4*)src)[j];
    dp[2*j]   = __half2(__float2half(v.x), __float2half(v.y));
    dp[2*j+1] = __half2(__float2half(v.z), __float2half(v.w));
}

// ---------------------------------------------------------------------------
// Kernel 1: QKV GEMM = xh * wh, single fp16 MMA (fp32 accum) per product.
// CTA 128x128, 4 warps (64x64), KC=64 double-buffered, 3 CTAs/SM. (R11 form)
// ---------------------------------------------------------------------------
#define KCG      64
#define GSTR_B   144                 // 128B data + 16B pad
#define GTILE_B  (128*GSTR_B)        // 18432
#define GSTAGE_B (2*GTILE_B)         // 36864

__device__ __forceinline__ void gemm_load(uint32_t sdst, int tid, int k0, int m0, int n0)
{
#pragma unroll
    for (int i = 0; i < 16; i++) {
        const int tile = i >> 3;                 // 0 xh, 1 wh
        int idx = ((i & 7) << 7) + tid;          // 0..1023
        int row = idx >> 3, q = idx & 7;
        const __half* g =
            (tile == 0) ? g_xh + (size_t)(m0 + row) * CDIM :
                          g_wh + (size_t)(n0 + row) * CDIM;
        CP_ASYNC(sdst + tile * GTILE_B + row * GSTR_B + q * 16, g + k0 + q * 8);
    }
}

__global__ __launch_bounds__(128, 3) void qkv_gemm_mma(const float* __restrict__ bias)
{
    extern __shared__ char smg[];
    const uint32_t sbase = smem_to_u32(smg);
    const int tid = threadIdx.x, lane = tid & 31, wid = tid >> 5;
    const int m0 = blockIdx.y * 128, n0 = blockIdx.x * 128;
    const int wm = wid & 1, wn = wid >> 1;

    float acc[4][8][4];
#pragma unroll
    for (int mi = 0; mi < 4; mi++)
#pragma unroll
        for (int nj = 0; nj < 8; nj++)
#pragma unroll
            for (int c = 0; c < 4; c++) acc[mi][nj][c] = 0.f;

    gemm_load(sbase, tid, 0, m0, n0);
    CP_COMMIT();

    const int NCH = CDIM / KCG;     // 16
    for (int c = 0; c < NCH; c++) {
        const int buf = c & 1;
        if (c + 1 < NCH) {
            gemm_load(sbase + (buf ^ 1) * GSTAGE_B, tid, (c + 1) * KCG, m0, n0);
            CP_COMMIT();
            CP_WAIT1();
        } else {
            CP_WAIT0();
        }
        __syncthreads();

        const uint32_t bb = sbase + buf * GSTAGE_B;
#pragma unroll
        for (int ks = 0; ks < 4; ks++) {
            const uint32_t coff = (ks * 16 + ((lane >> 4) << 3)) * 2;
            uint32_t ah[4][4];
#pragma unroll
            for (int mi = 0; mi < 4; mi++) {
                uint32_t ra = bb + (wm * 64 + mi * 16 + (lane & 15)) * GSTR_B + coff;
                ldsm4(ah[mi], ra);
            }
#pragma unroll
            for (int g2 = 0; g2 < 4; g2++) {
                uint32_t bh4[4];
                uint32_t rb = bb + GTILE_B +
                              (wn * 64 + g2 * 16 + (lane & 15)) * GSTR_B + coff;
                ldsm4(bh4, rb);
#pragma unroll
                for (int mi = 0; mi < 4; mi++) {
                    mma_f16(acc[mi][2*g2],   ah[mi], bh4[0], bh4[2]);
                    mma_f16(acc[mi][2*g2+1], ah[mi], bh4[1], bh4[3]);
                }
            }
        }
        __syncthreads();
    }

    // epilogue: +bias; Q scaled; all regions -> fp16
    const int nb = n0 + wn * 64;
    const int region = nb >> 10;
    const int h = (nb & 1023) >> 6;
    __half* dh = region == 0 ? g_qh : region == 1 ? g_kh : g_vh;
    const float scale = (region == 0) ? QSCALE : 1.0f;

#pragma unroll
    for (int mi = 0; mi < 4; mi++) {
#pragma unroll
        for (int rr = 0; rr < 2; rr++) {
            const int m = m0 + wm * 64 + mi * 16 + (lane >> 2) + rr * 8;
            const int b = m >> 11, t = m & 2047;
            const size_t roff = (((size_t)b * HEADS + h) * TSEQ + t) * HD;
#pragma unroll
            for (int nj = 0; nj < 8; nj++) {
                const int d = nj * 8 + 2 * (lane & 3);
                float2 bv = *(const float2*)(bias + nb + d);
                float v0 = (acc[mi][nj][rr*2+0] + bv.x) * scale;
                float v1 = (acc[mi][nj][rr*2+1] + bv.y) * scale;
                *(__half2*)(dh + roff + d) =
                    __half2(__float2half(v0), __float2half(v1));
            }
        }
    }
}

// ---------------------------------------------------------------------------
// Kernel 2: flash attention, fp16 mma.sync (fp32 accum).
// 4 warps x 32 q-rows (two 16-row m-tiles per warp): each K/V ldsm feeds
// both m-tiles -> half the LDS traffic per MMA vs the 8-warp version.
// 2-buffer KV loop, 128 threads, 2 CTAs/SM.
// ---------------------------------------------------------------------------
#define ASTR_B   144                // 64 fp16 (128B) + 16B pad
#define QTILE_B  (128*ASTR_B)       // 18432
#define KTILE_B  (64*ASTR_B)        // 9216
#define ABUF0    QTILE_B            // 18432
#define ABUF_B   (2*KTILE_B)        // 18432 (kh, vh)

__device__ __forceinline__ void kv_load(uint32_t sbase, int tid, size_t krow0,
                                        int kb, int buf)
{
#pragma unroll
    for (int i = 0; i < 8; i++) {
        const int arr = i >> 2;                // 0 kh, 1 vh
        int rem = ((i & 3) << 7) + tid;        // 0..511
        int row = rem >> 3, q = rem & 7;
        const __half* g = (arr == 0 ? g_kh : g_vh) +
                          (krow0 + (size_t)kb * 64 + row) * HD + q * 8;
        CP_ASYNC(sbase + ABUF0 + buf * ABUF_B + arr * KTILE_B + row * ASTR_B + q * 16, g);
    }
}

__global__ __launch_bounds__(128, 2) void attn_mma(float* __restrict__ out)
{
    extern __shared__ char sma[];
    const uint32_t sbase = smem_to_u32(sma);
    const int tid = threadIdx.x, lane = tid & 31, wid = tid >> 5;  // 4 warps
    const int qbi = gridDim.x - 1 - blockIdx.x;
    const int bh = blockIdx.y;
    const int kmax = 2 * qbi + 2;
    const size_t qrow0 = (size_t)bh * TSEQ + (size_t)qbi * 128;
    const size_t krow0 = (size_t)bh * TSEQ;

    // Q (fp16, pre-scaled) -> smem: 128 rows x 8 x 16B = 1024 chunks / 128 thr
#pragma unroll
    for (int i = 0; i < 8; i++) {
        int rem = (i << 7) + tid;               // 0..1023
        int row = rem >> 3, q = rem & 7;
        const __half* g = g_qh + (qrow0 + row) * HD + q * 8;
        CP_ASYNC(sbase + row * ASTR_B + q * 16, g);
    }
    CP_COMMIT();
    kv_load(sbase, tid, krow0, 0, 0);
    CP_COMMIT();
    CP_WAIT1();
    __syncthreads();

    // Q fragments for two m-tiles (rows wid*32 + mt*16 + ...)
    uint32_t qfh[2][4][4];
#pragma unroll
    for (int mt = 0; mt < 2; mt++)
#pragma unroll
        for (int ks = 0; ks < 4; ks++) {
            uint32_t a = sbase + (wid * 32 + mt * 16 + (lane & 15)) * ASTR_B +
                         (ks * 16 + ((lane >> 4) << 3)) * 2;
            ldsm4(qfh[mt][ks], a);
        }

    float o[2][8][4];
#pragma unroll
    for (int mt = 0; mt < 2; mt++)
#pragma unroll
        for (int nj = 0; nj < 8; nj++)
#pragma unroll
            for (int c = 0; c < 4; c++) o[mt][nj][c] = 0.f;
    float mrow[2][2], lrow[2][2];
#pragma unroll
    for (int mt = 0; mt < 2; mt++) {
        mrow[mt][0] = -1e30f; mrow[mt][1] = -1e30f;
        lrow[mt][0] = 0.f;    lrow[mt][1] = 0.f;
    }

    for (int kb = 0; kb < kmax; kb++) {
        const int buf = kb & 1;
        if (kb + 1 < kmax) {
            kv_load(sbase, tid, krow0, kb + 1, buf ^ 1);
            CP_COMMIT();
            CP_WAIT1();
        } else {
            CP_WAIT0();
        }
        __syncthreads();

        const bool active = (kb * 64 <= qbi * 128 + wid * 32 + 31);
        if (active) {
            // ---- S = qh * kh for both m-tiles; K frags loaded once ----
            float s[2][8][4];
#pragma unroll
            for (int mt = 0; mt < 2; mt++)
#pragma unroll
                for (int nj = 0; nj < 8; nj++)
#pragma unroll
                    for (int c = 0; c < 4; c++) s[mt][nj][c] = 0.f;

            const uint32_t kbase = sbase + ABUF0 + buf * ABUF_B;
#pragma unroll
            for (int ks = 0; ks < 4; ks++) {
                const uint32_t coff = (ks * 16 + ((lane >> 4) << 3)) * 2;
#pragma unroll
                for (int gp = 0; gp < 2; gp++) {
                    uint32_t ka[4], kb4[4];
                    uint32_t ra = kbase + (gp * 32 + (lane & 15)) * ASTR_B + coff;
                    uint32_t rb = ra + 16 * ASTR_B;
                    ldsm4(ka,  ra);
                    ldsm4(kb4, rb);
#pragma unroll
                    for (int mt = 0; mt < 2; mt++) {
                        mma_f16(s[mt][4*gp+0], qfh[mt][ks], ka[0],  ka[2]);
                        mma_f16(s[mt][4*gp+1], qfh[mt][ks], ka[1],  ka[3]);
                        mma_f16(s[mt][4*gp+2], qfh[mt][ks], kb4[0], kb4[2]);
                        mma_f16(s[mt][4*gp+3], qfh[mt][ks], kb4[1], kb4[3]);
                    }
                }
            }

            // ---- causal mask (diagonal band) ----
            if (kb >= 2 * qbi) {
                const int tb = kb * 64 + 2 * (lane & 3);
#pragma unroll
                for (int mt = 0; mt < 2; mt++) {
                    const int q1 = qbi * 128 + wid * 32 + mt * 16 + (lane >> 2);
#pragma unroll
                    for (int nj = 0; nj < 8; nj++) {
                        const int t0 = tb + 8 * nj;
                        if (t0     > q1)     s[mt][nj][0] = -1e30f;
                        if (t0 + 1 > q1)     s[mt][nj][1] = -1e30f;
                        if (t0     > q1 + 8) s[mt][nj][2] = -1e30f;
                        if (t0 + 1 > q1 + 8) s[mt][nj][3] = -1e30f;
                    }
                }
            }

            // ---- online softmax (base-2) per m-tile ----
#pragma unroll
            for (int mt = 0; mt < 2; mt++) {
                float mx1 = -1e30f, mx2 = -1e30f;
#pragma unroll
                for (int nj = 0; nj < 8; nj++) {
                    mx1 = fmaxf(mx1, fmaxf(s[mt][nj][0], s[mt][nj][1]));
                    mx2 = fmaxf(mx2, fmaxf(s[mt][nj][2], s[mt][nj][3]));
                }
                mx1 = fmaxf(mx1, __shfl_xor_sync(0xffffffffu, mx1, 1));
                mx1 = fmaxf(mx1, __shfl_xor_sync(0xffffffffu, mx1, 2));
                mx2 = fmaxf(mx2, __shfl_xor_sync(0xffffffffu, mx2, 1));
                mx2 = fmaxf(mx2, __shfl_xor_sync(0xffffffffu, mx2, 2));
                const float mn1 = fmaxf(mrow[mt][0], mx1);
                const float mn2 = fmaxf(mrow[mt][1], mx2);
                const float a1 = exp2f(mrow[mt][0] - mn1);
                const float a2 = exp2f(mrow[mt][1] - mn2);
                float rs1 = 0.f, rs2 = 0.f;
#pragma unroll
                for (int nj = 0; nj < 8; nj++) {
                    s[mt][nj][0] = exp2f(s[mt][nj][0] - mn1);
                    s[mt][nj][1] = exp2f(s[mt][nj][1] - mn1);
                    s[mt][nj][2] = exp2f(s[mt][nj][2] - mn2);
                    s[mt][nj][3] = exp2f(s[mt][nj][3] - mn2);
                    rs1 += s[mt][nj][0] + s[mt][nj][1];
                    rs2 += s[mt][nj][2] + s[mt][nj][3];
                }
                rs1 += __shfl_xor_sync(0xffffffffu, rs1, 1);
                rs1 += __shfl_xor_sync(0xffffffffu, rs1, 2);
                rs2 += __shfl_xor_sync(0xffffffffu, rs2, 1);
                rs2 += __shfl_xor_sync(0xffffffffu, rs2, 2);
                lrow[mt][0] = lrow[mt][0] * a1 + rs1;
                lrow[mt][1] = lrow[mt][1] * a2 + rs2;
                mrow[mt][0] = mn1;  mrow[mt][1] = mn2;
#pragma unroll
                for (int nj = 0; nj < 8; nj++) {
                    o[mt][nj][0] *= a1; o[mt][nj][1] *= a1;
                    o[mt][nj][2] *= a2; o[mt][nj][3] *= a2;
                }
            }

            // ---- O += P V; V frags loaded once per (kt,g2) ----
            const uint32_t vbase = kbase + KTILE_B;
#pragma unroll
            for (int kt = 0; kt < 4; kt++) {
                uint32_t ph[2][4];
#pragma unroll
                for (int mt = 0; mt < 2; mt++) {
                    const float* p0 = s[mt][2 * kt];
                    const float* p1 = s[mt][2 * kt + 1];
                    ph[mt][0] = pack2h(__float2half(p0[0]), __float2half(p0[1]));
                    ph[mt][1] = pack2h(__float2half(p0[2]), __float2half(p0[3]));
                    ph[mt][2] = pack2h(__float2half(p1[0]), __float2half(p1[1]));
                    ph[mt][3] = pack2h(__float2half(p1[2]), __float2half(p1[3]));
                }
#pragma unroll
                for (int g2 = 0; g2 < 4; g2++) {
                    uint32_t vh4[4];
                    uint32_t rb = vbase + (kt * 16 + (lane & 15)) * ASTR_B +
                                  (g2 * 16 + ((lane >> 4) << 3)) * 2;
                    ldsm4t(vh4, rb);
#pragma unroll
                    for (int mt = 0; mt < 2; mt++) {
                        mma_f16(o[mt][2*g2],   ph[mt], vh4[0], vh4[1]);
                        mma_f16(o[mt][2*g2+1], ph[mt], vh4[2], vh4[3]);
                    }
                }
            }
        }
        __syncthreads();
    }

    // epilogue
    const int b = bh >> 4, h = bh & 15;
#pragma unroll
    for (int mt = 0; mt < 2; mt++) {
        const float inv1 = 1.f / lrow[mt][0], inv2 = 1.f / lrow[mt][1];
        const int t1 = qbi * 128 + wid * 32 + mt * 16 + (lane >> 2);
        float* o1p = out + ((size_t)b * TSEQ + t1) * CDIM + h * 64 + 2 * (lane & 3);
        float* o2p = o1p + (size_t)8 * CDIM;
#pragma unroll
        for (int nj = 0; nj < 8; nj++) {
            *(float2*)(o1p + 8 * nj) =
                make_float2(o[mt][nj][0] * inv1, o[mt][nj][1] * inv1);
            *(float2*)(o2p + 8 * nj) =
                make_float2(o[mt][nj][2] * inv2, o[mt][nj][3] * inv2);
        }
    }
}

// ---------------------------------------------------------------------------
extern "C" void kernel_launch(void* const* d_in, const int* in_sizes, int n_in,
                              void* d_out, int out_size)
{
    (void)in_sizes; (void)n_in; (void)out_size;
    const float* x  = (const float*)d_in[0];
    const float* w  = (const float*)d_in[1];
    const float* bb = (const float*)d_in[2];
    float* out = (float*)d_out;

    const int nx4 = BT * CDIM / 4;
    const int nw4 = NQKV * CDIM / 4;
    conv_all<<<(nx4 + nw4 + 255) / 256, 256>>>(x, w, nx4, nw4);

    const int gsmem = 2 * GSTAGE_B;                     // 73728
    cudaFuncSetAttribute((const void*)qkv_gemm_mma,
                         cudaFuncAttributeMaxDynamicSharedMemorySize, gsmem);
    dim3 gg(NQKV / 128, BT / 128);                      // (24, 64)
    qkv_gemm_mma<<<gg, 128, gsmem>>>(bb);

    const int asmem = ABUF0 + 2 * ABUF_B;               // 55296
    cudaFuncSetAttribute((const void*)attn_mma,
                         cudaFuncAttributeMaxDynamicSharedMemorySize, asmem);
    dim3 ga(TSEQ / 128, NB * HEADS);                    // (16, 64)
    attn_mma<<<ga, 128, asmem>>>(out);
}